// round 13
// baseline (speedup 1.0000x reference)
#include <cuda_runtime.h>
#include <math.h>

#define LL 128
#define DD 2048
#define BSZ 32
#define TT 2048
#define NC 20
#define SLOT 16384

// ---------------- device scratch ----------------
// raw partial dot matrices, row-major 128x128:
// z 0..127  : LCS pair p=z>>2, K-quarter q=z&3 (koff=q*512)
// z 128..191: FSD-M pair p=(z-128)>>1, K-half h (koff=h*512)
// z 192..255: FSD-G pair p=(z-192)>>1, K-half h (koff=1024+h*512)
__device__ float g_S[256 * SLOT];
__device__ float g_rn[5 * 4096];     // 0 lcs, 1 act-m, 2 act-g, 3 bak-m, 4 bak-g
__device__ float g_bstats[BSZ * 5];
__device__ float g_dp[64];
__device__ int   g_ctr;

__device__ __forceinline__ float warpSum(float v) {
    #pragma unroll
    for (int o = 16; o > 0; o >>= 1) v += __shfl_down_sync(0xffffffffu, v, o);
    return v;
}

// ---------------- 1) warp-per-row norms + batch stats ----------------
__global__ void __launch_bounds__(256)
prep_kernel(const float* __restrict__ lcs,
            const float* __restrict__ fa,
            const float* __restrict__ fb,
            const float* __restrict__ att,
            const float* __restrict__ cas,
            const float* __restrict__ fi,
            const float* __restrict__ fc,
            const float* __restrict__ fbk) {
    int t = threadIdx.x;
    int w = t >> 5, lane = t & 31;

    if (blockIdx.x < 512) {
        int r = blockIdx.x * 8 + w;     // row 0..4095
        const float4* lrow = (const float4*)(lcs + (size_t)r * DD);
        const float4* arow = (const float4*)(fa  + (size_t)r * DD);
        const float4* brow = (const float4*)(fb  + (size_t)r * DD);
        float s_l = 0.f, s_am = 0.f, s_ag = 0.f, s_bm = 0.f, s_bg = 0.f;
        #pragma unroll 4
        for (int i = 0; i < 16; i++) {
            int q = i * 32 + lane;
            float4 v = lrow[q];
            s_l += v.x*v.x + v.y*v.y + v.z*v.z + v.w*v.w;
            float4 a = arow[q];
            float sa = a.x*a.x + a.y*a.y + a.z*a.z + a.w*a.w;
            float4 b = brow[q];
            float sb = b.x*b.x + b.y*b.y + b.z*b.z + b.w*b.w;
            if (i < 8) { s_am += sa; s_bm += sb; }
            else       { s_ag += sa; s_bg += sb; }
        }
        s_l  = warpSum(s_l);
        s_am = warpSum(s_am);
        s_ag = warpSum(s_ag);
        s_bm = warpSum(s_bm);
        s_bg = warpSum(s_bg);
        if (lane == 0) {
            g_rn[0 * 4096 + r] = 1.0f / sqrtf(s_l);
            g_rn[1 * 4096 + r] = 1.0f / sqrtf(s_am);
            g_rn[2 * 4096 + r] = 1.0f / sqrtf(s_ag);
            g_rn[3 * 4096 + r] = 1.0f / sqrtf(s_bm);
            g_rn[4 * 4096 + r] = 1.0f / sqrtf(s_bg);
        }
    } else {
        __shared__ float red[5][8];
        int b = blockIdx.x - 512;
        float guide = 0.f, sp = 0.f, ni = 0.f, nc = 0.f, nb = 0.f;
        for (int q = t; q < TT; q += 256) {
            float c  = cas[((size_t)b * TT + q) * 21 + 20];
            float a0 = att[((size_t)b * TT + q) * 3 + 0];
            float a1 = att[((size_t)b * TT + q) * 3 + 1];
            guide += fabsf(1.0f - c - a0);
            sp += a0 + a1;
        }
        for (int q = t; q < DD; q += 256) {
            float x;
            x = fi [b * DD + q]; ni += x * x;
            x = fc [b * DD + q]; nc += x * x;
            x = fbk[b * DD + q]; nb += x * x;
        }
        float vals[5] = {guide, sp, ni, nc, nb};
        #pragma unroll
        for (int k = 0; k < 5; k++) {
            float s = warpSum(vals[k]);
            if (lane == 0) red[k][w] = s;
        }
        __syncthreads();
        if (t == 0) {
            float s0=0,s1=0,s2=0,s3=0,s4=0;
            #pragma unroll
            for (int w2 = 0; w2 < 8; w2++) {
                s0 += red[0][w2]; s1 += red[1][w2]; s2 += red[2][w2];
                s3 += red[3][w2]; s4 += red[4][w2];
            }
            g_bstats[b*5+0] = s0;
            g_bstats[b*5+1] = s1;
            g_bstats[b*5+2] = sqrtf(s2);
            g_bstats[b*5+3] = sqrtf(s3);
            g_bstats[b*5+4] = sqrtf(s4);
        }
    }
}

// ---------------- 2) tf32 mma split-K GEMM (raw partials) ------------------
// 256 blocks x 256 threads, 8 warps of 32x64, K=512 each, 2 blocks/SM.
#define SIM_STRIDE 36
#define SIM_TILE   (128 * SIM_STRIDE)
#define SIM_SMEM   (4 * SIM_TILE * 4)

__device__ __forceinline__ void cp16(float* smem_dst, const float* gsrc) {
    unsigned s = (unsigned)__cvta_generic_to_shared(smem_dst);
    asm volatile("cp.async.cg.shared.global [%0], [%1], 16;\n" :: "r"(s), "l"(gsrc));
}

__global__ void __launch_bounds__(256, 2)
sim_kernel(const float* __restrict__ lcs,
           const float* __restrict__ fa,
           const float* __restrict__ fb,
           const int* __restrict__ pos,
           const int* __restrict__ neg) {
    extern __shared__ float sh[];
    float* Abuf = sh;
    float* Bbuf = sh + 2 * SIM_TILE;

    int z = blockIdx.x;
    int t = threadIdx.x;
    int w = t >> 5, lane = t & 31;
    int wm = w >> 1, wn = w & 1;        // wm 0..3 (32-row stripes), wn 0..1 (64-col)
    int lg = lane >> 2, lc = lane & 3;

    int p, koff, kind;
    if (z < 128)      { kind = 0; p = z >> 2;        koff = (z & 3) * 512; }
    else if (z < 192) { kind = 1; p = (z - 128) >> 1; koff = ((z - 128) & 1) * 512; }
    else              { kind = 2; p = (z - 192) >> 1; koff = 1024 + ((z - 192) & 1) * 512; }

    int ia, ib;
    if (p < 16) { ia = pos[2*p]; ib = pos[2*p+1]; }
    else        { ia = neg[2*(p-16)]; ib = neg[2*(p-16)+1]; }

    const float *abase, *bbase;
    if (kind == 0) {
        abase = lcs + (size_t)ia * LL * DD + koff;
        bbase = lcs + (size_t)ib * LL * DD + koff;
    } else {
        abase = fa + (size_t)ia * LL * DD + koff;
        bbase = ((p < 16) ? fa : fb) + (size_t)ib * LL * DD + koff;
    }
    float* out = g_S + (size_t)z * SLOT;

    float acc[2][8][4];
    #pragma unroll
    for (int mt = 0; mt < 2; mt++)
        #pragma unroll
        for (int nt = 0; nt < 8; nt++)
            #pragma unroll
            for (int j = 0; j < 4; j++) acc[mt][nt][j] = 0.f;

    #pragma unroll
    for (int u = 0; u < 4; u++) {
        int fq = u * 256 + t;
        int r = fq >> 3, cq = fq & 7;
        cp16(Abuf + r * SIM_STRIDE + cq * 4, abase + (size_t)r * DD + cq * 4);
        cp16(Bbuf + r * SIM_STRIDE + cq * 4, bbase + (size_t)r * DD + cq * 4);
    }
    asm volatile("cp.async.commit_group;\n");

    int buf = 0;
    for (int it = 0; it < 16; it++) {
        if (it + 1 < 16) {
            float* Ad = Abuf + (buf ^ 1) * SIM_TILE;
            float* Bd = Bbuf + (buf ^ 1) * SIM_TILE;
            int kt = (it + 1) * 32;
            #pragma unroll
            for (int u = 0; u < 4; u++) {
                int fq = u * 256 + t;
                int r = fq >> 3, cq = fq & 7;
                cp16(Ad + r * SIM_STRIDE + cq * 4, abase + (size_t)r * DD + kt + cq * 4);
                cp16(Bd + r * SIM_STRIDE + cq * 4, bbase + (size_t)r * DD + kt + cq * 4);
            }
        }
        asm volatile("cp.async.commit_group;\n");
        asm volatile("cp.async.wait_group 1;\n");
        __syncthreads();

        const float* As = Abuf + buf * SIM_TILE;
        const float* Bs = Bbuf + buf * SIM_TILE;
        #pragma unroll
        for (int ks = 0; ks < 4; ks++) {
            unsigned a[2][4], b[8][2];
            int c0 = ks * 8 + lc;
            #pragma unroll
            for (int mt = 0; mt < 2; mt++) {
                const float* base = As + (wm*32 + mt*16 + lg) * SIM_STRIDE + c0;
                a[mt][0] = __float_as_uint(base[0]);
                a[mt][1] = __float_as_uint(base[8 * SIM_STRIDE]);
                a[mt][2] = __float_as_uint(base[4]);
                a[mt][3] = __float_as_uint(base[8 * SIM_STRIDE + 4]);
            }
            #pragma unroll
            for (int nt = 0; nt < 8; nt++) {
                const float* base = Bs + (wn*64 + nt*8 + lg) * SIM_STRIDE + c0;
                b[nt][0] = __float_as_uint(base[0]);
                b[nt][1] = __float_as_uint(base[4]);
            }
            #pragma unroll
            for (int mt = 0; mt < 2; mt++)
                #pragma unroll
                for (int nt = 0; nt < 8; nt++)
                    asm volatile(
                        "mma.sync.aligned.m16n8k8.row.col.f32.tf32.tf32.f32 "
                        "{%0,%1,%2,%3}, {%4,%5,%6,%7}, {%8,%9}, {%0,%1,%2,%3};"
                        : "+f"(acc[mt][nt][0]), "+f"(acc[mt][nt][1]),
                          "+f"(acc[mt][nt][2]), "+f"(acc[mt][nt][3])
                        : "r"(a[mt][0]), "r"(a[mt][1]), "r"(a[mt][2]), "r"(a[mt][3]),
                          "r"(b[nt][0]), "r"(b[nt][1]));
        }
        __syncthreads();
        buf ^= 1;
    }

    #pragma unroll
    for (int mt = 0; mt < 2; mt++) {
        int row0 = wm*32 + mt*16 + lg;
        #pragma unroll
        for (int nt = 0; nt < 8; nt++) {
            int col0 = wn*64 + nt*8 + 2*lc;
            *(float2*)(out + row0 * 128 + col0) =
                make_float2(acc[mt][nt][0], acc[mt][nt][1]);
            *(float2*)(out + (row0 + 8) * 128 + col0) =
                make_float2(acc[mt][nt][2], acc[mt][nt][3]);
        }
    }
}

// ---------------- 3) wavefront DP + fused final ----------------
#define DP_STRIDE 130
#define DP_SMEM_BYTES ((2 * 128 * DP_STRIDE + 3 * 132) * 4)

__global__ void __launch_bounds__(128, 1)
dp_kernel(const int* __restrict__ pos, const int* __restrict__ neg,
          const float* __restrict__ xi, const float* __restrict__ xc,
          const float* __restrict__ xb, const float* __restrict__ vid,
          float* __restrict__ out) {
    extern __shared__ float sh[];
    float* Ms = sh;
    float* Gs = sh + 128 * DP_STRIDE;
    float* Pr = sh + 2 * 128 * DP_STRIDE;
    __shared__ bool isLast;

    int blk = blockIdx.x;
    int t = threadIdx.x;
    bool is_fsd = blk >= 32;
    int p = is_fsd ? blk - 32 : blk;
    int ia, ib;
    if (p < 16) { ia = pos[2*p]; ib = pos[2*p+1]; }
    else        { ia = neg[2*(p-16)]; ib = neg[2*(p-16)+1]; }

    if (!is_fsd) {
        const float* s0 = g_S + (size_t)(4*p + 0) * SLOT;
        const float* s1 = g_S + (size_t)(4*p + 1) * SLOT;
        const float* s2 = g_S + (size_t)(4*p + 2) * SLOT;
        const float* s3 = g_S + (size_t)(4*p + 3) * SLOT;
        const float* rnA = g_rn + ia * LL;
        float rbt = g_rn[ib * LL + t];
        for (int k = 0; k < 128; k++) {
            int q = k * 128 + t;
            float v = (s0[q] + s1[q] + s2[q] + s3[q]) * rnA[k] * rbt;
            Ms[k * DP_STRIDE + t] = fmaxf(0.f, (v - 0.8f) * 5.0f);
        }
    } else {
        const float* m0 = g_S + (size_t)(128 + 2*p) * SLOT;
        const float* m1 = g_S + (size_t)(128 + 2*p + 1) * SLOT;
        const float* g0 = g_S + (size_t)(192 + 2*p) * SLOT;
        const float* g1 = g_S + (size_t)(192 + 2*p + 1) * SLOT;
        const float* rnMA = g_rn + 1*4096 + ia * LL;
        const float* rnGA = g_rn + 2*4096 + ia * LL;
        float rMBt = g_rn[((p < 16) ? 1 : 3)*4096 + ib * LL + t];
        float rGBt = g_rn[((p < 16) ? 2 : 4)*4096 + ib * LL + t];
        for (int k = 0; k < 128; k++) {
            int q = k * 128 + t;
            Ms[k * DP_STRIDE + t] = (m0[q] + m1[q]) * rnMA[k] * rMBt;
            Gs[k * DP_STRIDE + t] = (g0[q] + g1[q]) * rnGA[k] * rGBt;
        }
    }
    for (int q = t; q < 3 * 132; q += 128) Pr[q] = 0.f;
    __syncthreads();

    float* P1 = Pr;
    float* P2 = Pr + 132;
    float* P0 = Pr + 264;

    const float S2L = 14.42695040888963f;    // 10 * log2(e)
    const float KLN = 0.06931471805599453f;  // 0.1 * ln(2)

    float cur = 0.f;
    int base = t * DP_STRIDE;

    for (int s = 0; s < 255; s++) {
        int j = s - t;
        bool act = ((unsigned)j < 128u);
        float up = P1[t];
        float dg = P2[t];
        float lf = cur;
        if (j == 0) { lf = 0.f; dg = 0.f; }
        if (act) {
            float nv;
            if (is_fsd) {
                float m = Ms[base + j];
                float g = Gs[base + j];
                float a0 = dg;
                float a1 = g + up;
                float a2 = g + lf;
                float m12 = fmaxf(a1, a2), n12 = fminf(a1, a2);
                float mx  = fmaxf(a0, m12), mn = fminf(a0, m12);
                float tt = -mx * S2L;
                float x1 = fmaf(mn,  S2L, tt);
                float x2 = fmaf(n12, S2L, tt);
                float e1, e2, lgv;
                asm("ex2.approx.ftz.f32 %0, %1;" : "=f"(e1) : "f"(x1));
                asm("ex2.approx.ftz.f32 %0, %1;" : "=f"(e2) : "f"(x2));
                float se = 1.0f + e1 + e2;
                asm("lg2.approx.ftz.f32 %0, %1;" : "=f"(lgv) : "f"(se));
                nv = fmaf(lgv, KLN, m + mx);
            } else {
                float m = Ms[base + j];
                nv = (m > 0.5f) ? (dg + m) : fmaxf(up, lf);
            }
            cur = nv;
            P0[t + 1] = nv;
        }
        __syncthreads();
        float* tmp = P2; P2 = P1; P1 = P0; P0 = tmp;
    }
    if (t == 127) g_dp[blk] = cur;

    // ---- last-block-done fused final ----
    __threadfence();
    __syncthreads();
    if (t == 0) {
        int c = atomicAdd(&g_ctr, 1);
        isLast = (c == 63);
    }
    __syncthreads();
    if (!isLast) return;
    if (t == 0) g_ctr = 0;

    if (t < 32) {
        int b = t;
        const float EPS = 1e-45f;
        float s = 0.f, li = 0.f, lcc = 0.f;
        #pragma unroll
        for (int c = 0; c < NC; c++) {
            float v = vid[b * NC + c];
            s += v;
            li  += __logf(xi[b * 21 + c] + EPS) * v;
            lcc += __logf(xc[b * 21 + c] + EPS) * v;
        }
        lcc += __logf(xc[b * 21 + 20] + EPS);
        float lb = __logf(xb[b * 21 + 20] + EPS);
        float cls_b = -(li / s) - (lcc / (s + 1.0f)) - lb;

        float guide = g_bstats[b*5+0];
        float sp    = g_bstats[b*5+1];
        float ni    = g_bstats[b*5+2];
        float nc2   = g_bstats[b*5+3];
        float nb    = g_bstats[b*5+4];
        float f1 = fmaxf(50.0f - ni + nc2, 0.f);
        float f2 = fmaxf(50.0f - nc2 + nb, 0.f);
        float fsum = f1 + f2 + nb;
        float feat_b = fsum * fsum;

        float lcs_v = g_dp[b];
        float fsd_v = g_dp[32 + b];
        float sign = (b < 16) ? -1.0f : 1.0f;

        float tot = cls_b * (1.0f / 32.0f)
                  + guide * (1.0f / 32.0f)
                  + 5e-5f * feat_b * (1.0f / 32.0f)
                  + 2e-4f * sp * (1.0f / 64.0f)
                  + 0.1f * sign * lcs_v * (1.0f / 16.0f)
                  + 0.1f * sign * fsd_v * (1.0f / 16.0f);

        tot = warpSum(tot);
        if (b == 0) out[0] = tot;
    }
}

// ---------------- launch ----------------
extern "C" void kernel_launch(void* const* d_in, const int* in_sizes, int n_in,
                              void* d_out, int out_size) {
    const float* xi   = (const float*)d_in[0];
    const float* xc   = (const float*)d_in[1];
    const float* xb   = (const float*)d_in[2];
    const float* vid  = (const float*)d_in[3];
    const float* att  = (const float*)d_in[4];
    const float* fi   = (const float*)d_in[5];
    const float* fc   = (const float*)d_in[6];
    const float* fbk  = (const float*)d_in[7];
    const float* cas  = (const float*)d_in[8];
    const float* lcs  = (const float*)d_in[9];
    const float* fa   = (const float*)d_in[10];
    const float* fb   = (const float*)d_in[11];
    const int*   pos  = (const int*)d_in[12];
    const int*   neg  = (const int*)d_in[13];
    float* out = (float*)d_out;

    // One-time resource init (first call is the uncaptured correctness run).
    static cudaStream_t s2 = nullptr;
    static cudaEvent_t ev0 = nullptr, ev1 = nullptr;
    if (s2 == nullptr) {
        cudaStreamCreate(&s2);
        cudaEventCreateWithFlags(&ev0, cudaEventDisableTiming);
        cudaEventCreateWithFlags(&ev1, cudaEventDisableTiming);
        cudaFuncSetAttribute(sim_kernel, cudaFuncAttributeMaxDynamicSharedMemorySize, SIM_SMEM);
        cudaFuncSetAttribute(dp_kernel, cudaFuncAttributeMaxDynamicSharedMemorySize, DP_SMEM_BYTES);
    }

    // Fork: sim (stream s2) runs concurrently with prep (default stream).
    cudaEventRecord(ev0, 0);
    cudaStreamWaitEvent(s2, ev0, 0);
    sim_kernel<<<256, 256, SIM_SMEM, s2>>>(lcs, fa, fb, pos, neg);
    cudaEventRecord(ev1, s2);

    prep_kernel<<<544, 256>>>(lcs, fa, fb, att, cas, fi, fc, fbk);

    // Join: dp needs both sim partials and prep norms.
    cudaStreamWaitEvent(0, ev1, 0);
    dp_kernel<<<64, 128, DP_SMEM_BYTES>>>(pos, neg, xi, xc, xb, vid, out);
}